// round 9
// baseline (speedup 1.0000x reference)
#include <cuda_runtime.h>
#include <cuda_fp16.h>
#include <cstdint>

#define T_TOK 16384
#define NE    8
#define DIN   1024
#define DOUT  1024
#define NA    8
#define RANK  16
#define BM    128
#define BN    128
#define BK    64                    // halfs per K-chunk (128 bytes)
#define KLORA (NA * RANK)           // 128
#define KEXT  (DIN + KLORA)         // 1152
#define NCHUNK (KEXT / BK)          // 18
#define MAX_TILES 144
#define RSTRIDE 72                  // smem row stride in halfs (64 + 8 pad, 144B)
#define ABY   (BM * RSTRIDE * 2)    // 18432 bytes per buffer
#define DSMEM_BYTES (4 * ABY)       // A0,A1,B0,B1 = 73728 (2 CTAs/SM)

// prep grid decomposition (flattened): 17 x 32 x 8 = 4352 blocks after the 144 inter blocks
#define PREP_X (DIN / 64 + 1)       // 17
#define PREP_Y (DOUT / 32)          // 32
#define NBLK_PREP (PREP_X * PREP_Y * NE)
#define NBLK_TOTAL (MAX_TILES + NBLK_PREP)

// ---------------- device scratch (static, no allocations) ----------------
__device__ __align__(256) __half g_xe[(size_t)T_TOK * KEXT];     // 37.7 MB [rn(x) | spread scaled inter]
__device__ __align__(256) __half g_wt[(size_t)NE * DOUT * KEXT]; // 18.9 MB [e][n][k]: rn(W^T) | rn(lora_B)

// ---------------- helpers ----------------
__device__ __forceinline__ uint32_t smem_u32(const void* p) {
    uint32_t a;
    asm("{ .reg .u64 t; cvta.to.shared.u64 t, %1; cvt.u32.u64 %0, t; }" : "=r"(a) : "l"(p));
    return a;
}
__device__ __forceinline__ void cp_async16(uint32_t dst, const void* src) {
    asm volatile("cp.async.cg.shared.global [%0], [%1], 16;"
                 :: "r"(dst), "l"(src) : "memory");
}
__device__ __forceinline__ void cp_async16p(uint32_t dst, const void* src, int srcsize) {
    asm volatile("cp.async.cg.shared.global [%0], [%1], 16, %2;"
                 :: "r"(dst), "l"(src), "r"(srcsize) : "memory");
}
__device__ __forceinline__ void ldsm_x4(uint32_t* r, uint32_t addr) {
    asm volatile("ldmatrix.sync.aligned.m8n8.x4.shared.b16 {%0,%1,%2,%3}, [%4];"
                 : "=r"(r[0]), "=r"(r[1]), "=r"(r[2]), "=r"(r[3]) : "r"(addr));
}

// Derive a row-tile from group_sizes. Returns false past the last tile.
__device__ __forceinline__ bool tile_lookup(const int* __restrict__ gs, int tile_id,
                                            int& row0, int& e, int& rows) {
    int cnt = 0, off = 0;
#pragma unroll
    for (int ee = 0; ee < NE; ee++) {
        int gsz = gs[ee];
        int nt  = (gsz + BM - 1) / BM;
        if (tile_id < cnt + nt) {
            int local = tile_id - cnt;
            row0 = off + local * BM;
            e    = ee;
            rows = min(BM, gsz - local * BM);
            return true;
        }
        cnt += nt;
        off += gsz;
    }
    return false;
}

// ---------------- kernel 1: fused prep (W transpose + Bext) AND lora_inter + x->fp16 ----------------
// blockIdx.x <  MAX_TILES            : lora_inter path (heavy blocks, start first)
// blockIdx.x >= MAX_TILES            : prep_w path (flattened 17 x 32 x 8)
__global__ __launch_bounds__(256) void prep_all_kernel(
    const float* __restrict__ x,
    const int*   __restrict__ gs,
    const int*   __restrict__ adap,
    const float* __restrict__ wgt,
    const float* __restrict__ lA,
    const float* __restrict__ lB,
    const float* __restrict__ lscale)
{
    __shared__ float smem_f[NA * 32 * RANK + BM * 33];   // union of both paths' needs

    int tid = threadIdx.x;

    if (blockIdx.x >= MAX_TILES) {
        // ================= prep_w path =================
        int bid = blockIdx.x - MAX_TILES;
        int bx  = bid % PREP_X;
        int by  = (bid / PREP_X) % PREP_Y;
        int e   = bid / (PREP_X * PREP_Y);
        int n0  = by * 32;
        int tx  = tid & 31;
        int ty  = tid >> 5;

        if (bx == DIN / 64) {
            // Bext: g_wt[e][n0+n][1024 + a*16+r] = rn(lora_B[a][e][r][n0+n])
            for (int f = tid; f < 32 * KLORA; f += 256) {
                int n = f >> 7;
                int j = f & 127;
                int a = j >> 4, r = j & 15;
                g_wt[((size_t)e * DOUT + n0 + n) * KEXT + DIN + j] =
                    __float2half_rn(lB[(((size_t)a * NE + e) * RANK + r) * DOUT + n0 + n]);
            }
            return;
        }

        float (*tile)[33] = (float(*)[33])smem_f;        // [64][33]
        int k0 = bx * 64;
#pragma unroll
        for (int i = 0; i < 64; i += 8)
            tile[i + ty][tx] = wgt[((size_t)e * DIN + k0 + i + ty) * DOUT + n0 + tx];
        __syncthreads();
#pragma unroll
        for (int nn = 0; nn < 4; nn++) {
            int n = nn * 8 + ty;
            __half2 h = __floats2half2_rn(tile[tx * 2][n], tile[tx * 2 + 1][n]);
            *(__half2*)&g_wt[((size_t)e * DOUT + n0 + n) * KEXT + k0 + tx * 2] = h;
        }
        return;
    }

    // ================= lora_inter path =================
    float (*as_)[32][RANK] = (float(*)[32][RANK])smem_f;            // [8][32][16]
    float (*xs)[33]        = (float(*)[33])(smem_f + NA * 32 * RANK); // [128][33]

    int row0, e, rows;
    if (!tile_lookup(gs, blockIdx.x, row0, e, rows)) return;

    int r  = tid & 15;
    int tg = tid >> 4;

    int   aj[8];
    float acc[8];
#pragma unroll
    for (int j = 0; j < 8; j++) {
        int tok = tg + j * 16;
        aj[j]  = (tok < rows) ? adap[row0 + tok] : 0;
        acc[j] = 0.f;
    }

    for (int k0 = 0; k0 < DIN; k0 += 32) {
#pragma unroll
        for (int it = 0; it < 4; it++) {
            int flat = (tid + it * 256) * 4;
            int tok  = flat >> 5;
            int kk   = flat & 31;
            float4 v = make_float4(0.f, 0.f, 0.f, 0.f);
            if (tok < rows) {
                v = *(const float4*)&x[(size_t)(row0 + tok) * DIN + k0 + kk];
                // fused fp16 conversion of x
                __half2* dst = (__half2*)&g_xe[(size_t)(row0 + tok) * KEXT + k0 + kk];
                dst[0] = __floats2half2_rn(v.x, v.y);
                dst[1] = __floats2half2_rn(v.z, v.w);
            }
            xs[tok][kk] = v.x; xs[tok][kk + 1] = v.y;
            xs[tok][kk + 2] = v.z; xs[tok][kk + 3] = v.w;
        }
#pragma unroll
        for (int it = 0; it < 4; it++) {
            int flat = (tid + it * 256) * 4;
            int a    = flat >> 9;
            int rem  = flat & 511;
            int kk   = rem >> 4;
            int rr   = rem & 15;
            float4 v = *(const float4*)&lA[((size_t)(a * NE + e) * DIN + k0 + kk) * RANK + rr];
            *(float4*)&as_[a][kk][rr] = v;
        }
        __syncthreads();
#pragma unroll
        for (int kk = 0; kk < 32; kk++)
#pragma unroll
            for (int j = 0; j < 8; j++)
                acc[j] += xs[tg + j * 16][kk] * as_[aj[j]][kk][r];
        __syncthreads();
    }

#pragma unroll
    for (int j = 0; j < 8; j++) {
        int tok = tg + j * 16;
        if (tok < rows) {
            __half hv = __float2half_rn(acc[j] * lscale[aj[j]]);
            __half hz = __float2half_rn(0.f);
            __half* dst = g_xe + (size_t)(row0 + tok) * KEXT + DIN + r;
#pragma unroll
            for (int a = 0; a < NA; a++) dst[a * RANK] = (a == aj[j]) ? hv : hz;
        }
    }
}

// ---------------- kernel 2: fp16 mma.sync GEMM, 128x128 tile, K = 1152 ----------------
__global__ __launch_bounds__(256, 2) void main_gemm_kernel(const int* __restrict__ gs,
                                                           float* __restrict__ out) {
    extern __shared__ char sm[];
    int row0, e, rows;
    if (!tile_lookup(gs, blockIdx.y, row0, e, rows)) return;

    int col0 = blockIdx.x * BN;
    int tid  = threadIdx.x;
    int lane = tid & 31;
    int wid  = tid >> 5;
    int wm   = (wid & 3) * 32;      // warp row base (4 warps in M)
    int wn   = (wid >> 2) * 64;     // warp col base (2 warps in N)
    int gi   = lane >> 2;
    int ti   = lane & 3;

    uint32_t sbase = smem_u32(sm);
    const __half* arow = g_xe + (size_t)row0 * KEXT;
    const __half* brow = g_wt + ((size_t)e * DOUT + col0) * KEXT;

    uint32_t aoff[2];
#pragma unroll
    for (int i = 0; i < 2; i++)
        aoff[i] = (uint32_t)((wm + i * 16 + (lane & 15)) * RSTRIDE + (lane >> 4) * 8) * 2;
    uint32_t boff[4];
#pragma unroll
    for (int p = 0; p < 4; p++)
        boff[p] = (uint32_t)((wn + p * 16 + ((lane >> 4) << 3) + (lane & 7)) * RSTRIDE
                             + (((lane >> 3) & 1) << 3)) * 2;

    float acc[2][8][4];
#pragma unroll
    for (int i = 0; i < 2; i++)
#pragma unroll
        for (int j = 0; j < 8; j++)
#pragma unroll
            for (int q = 0; q < 4; q++) acc[i][j][q] = 0.f;

    bool full = (rows == BM);
    auto load_chunk = [&](int c) {
        uint32_t ab = sbase + (c & 1) * ABY;
        uint32_t bb = sbase + 2 * ABY + (c & 1) * ABY;
        if (full) {
#pragma unroll
            for (int it = 0; it < 4; it++) {
                int f = tid + it * 256;
                int m = f >> 3, q = f & 7;
                cp_async16(ab + m * (RSTRIDE * 2) + q * 16,
                           arow + (size_t)m * KEXT + c * BK + q * 8);
                cp_async16(bb + m * (RSTRIDE * 2) + q * 16,
                           brow + (size_t)m * KEXT + c * BK + q * 8);
            }
        } else {
#pragma unroll
            for (int it = 0; it < 4; it++) {
                int f = tid + it * 256;
                int m = f >> 3, q = f & 7;
                cp_async16p(ab + m * (RSTRIDE * 2) + q * 16,
                            arow + (size_t)m * KEXT + c * BK + q * 8,
                            (m < rows) ? 16 : 0);
                cp_async16(bb + m * (RSTRIDE * 2) + q * 16,
                           brow + (size_t)m * KEXT + c * BK + q * 8);
            }
        }
    };

    load_chunk(0);
    asm volatile("cp.async.commit_group;" ::: "memory");

    for (int c = 0; c < NCHUNK; c++) {
        asm volatile("cp.async.wait_group 0;" ::: "memory");
        __syncthreads();

        if (c + 1 < NCHUNK) {
            load_chunk(c + 1);
            asm volatile("cp.async.commit_group;" ::: "memory");
        }

        uint32_t abase = sbase + (c & 1) * ABY;
        uint32_t bbase = sbase + 2 * ABY + (c & 1) * ABY;

#pragma unroll
        for (int t = 0; t < 4; t++) {
            uint32_t a[2][4], b[4][4];
#pragma unroll
            for (int i = 0; i < 2; i++) ldsm_x4(a[i], abase + aoff[i] + t * 32);
#pragma unroll
            for (int p = 0; p < 4; p++) ldsm_x4(b[p], bbase + boff[p] + t * 32);
#pragma unroll
            for (int i = 0; i < 2; i++)
#pragma unroll
                for (int j = 0; j < 8; j++) {
                    float* d = acc[i][j];
                    asm volatile(
                        "mma.sync.aligned.m16n8k16.row.col.f32.f16.f16.f32 "
                        "{%0,%1,%2,%3}, {%4,%5,%6,%7}, {%8,%9}, {%0,%1,%2,%3};"
                        : "+f"(d[0]), "+f"(d[1]), "+f"(d[2]), "+f"(d[3])
                        : "r"(a[i][0]), "r"(a[i][1]), "r"(a[i][2]), "r"(a[i][3]),
                          "r"(b[j >> 1][(j & 1) * 2]), "r"(b[j >> 1][(j & 1) * 2 + 1]));
                }
        }
    }

    // -------- epilogue: registers -> gmem --------
    float* obase = out + (size_t)row0 * DOUT + col0;
#pragma unroll
    for (int i = 0; i < 2; i++) {
        int r1 = wm + i * 16 + gi;
#pragma unroll
        for (int j = 0; j < 8; j++) {
            int cn = wn + j * 8 + ti * 2;
            if (r1 < rows)
                *(float2*)(obase + (size_t)r1 * DOUT + cn) =
                    make_float2(acc[i][j][0], acc[i][j][1]);
            if (r1 + 8 < rows)
                *(float2*)(obase + (size_t)(r1 + 8) * DOUT + cn) =
                    make_float2(acc[i][j][2], acc[i][j][3]);
        }
    }
}

// ---------------- launch ----------------
extern "C" void kernel_launch(void* const* d_in, const int* in_sizes, int n_in,
                              void* d_out, int out_size) {
    const float* x      = (const float*)d_in[0];
    const int*   gs     = (const int*)  d_in[1];
    const int*   adap   = (const int*)  d_in[2];
    const float* wgt    = (const float*)d_in[3];
    const float* lA     = (const float*)d_in[4];
    const float* lB     = (const float*)d_in[5];
    const float* lscale = (const float*)d_in[6];
    float*       out    = (float*)d_out;

    cudaFuncSetAttribute(main_gemm_kernel,
                         cudaFuncAttributeMaxDynamicSharedMemorySize, DSMEM_BYTES);

    prep_all_kernel<<<NBLK_TOTAL, 256>>>(x, gs, adap, wgt, lA, lB, lscale);
    main_gemm_kernel<<<dim3(DOUT / BN, MAX_TILES), 256, DSMEM_BYTES>>>(gs, out);
}

// round 12
// speedup vs baseline: 1.4946x; 1.4946x over previous
#include <cuda_runtime.h>
#include <cuda_fp16.h>
#include <cstdint>

#define T_TOK 16384
#define NE    8
#define DIN   1024
#define DOUT  1024
#define NA    8
#define RANK  16
#define BM    128
#define BN    128
#define BK    64                    // halfs per K-chunk (128 bytes)
#define KLORA (NA * RANK)           // 128
#define KEXT  (DIN + KLORA)         // 1152
#define NCHUNK (KEXT / BK)          // 18
#define NCHUNK_I (DIN / BK)         // 16 (inter-gemm: K = 1024 only)
#define MAX_TILES 144
#define RSTRIDE 72                  // smem row stride in halfs (64 + 8 pad, 144B)
#define ABY   (BM * RSTRIDE * 2)    // 18432 bytes per buffer
#define DSMEM_BYTES (4 * ABY)       // A0,A1,B0,B1 = 73728 (2 CTAs/SM)

// prep kernel block ranges (all light, memory-bound)
#define PB_XCONV 1024               // x -> fp16 (16 tokens per block)
#define PB_WT    4096               // W transpose (16 x 32 x 8)
#define PB_BEXT  256                // lora_B extension (32 x 8)
#define PB_AEXT  128                // A_ext build (1024 warps)
#define PB_TOTAL (PB_XCONV + PB_WT + PB_BEXT + PB_AEXT)

// ---------------- device scratch (static, no allocations) ----------------
__device__ __align__(256) __half g_xe[(size_t)T_TOK * KEXT];     // 37.7 MB [rn(x) | masked scaled inter]
__device__ __align__(256) __half g_wt[(size_t)NE * DOUT * KEXT]; // 18.9 MB [e][n][k]: rn(W^T) | rn(lora_B)
__device__ __align__(256) __half g_at[(size_t)NE * KLORA * DIN]; // 2 MB [e][j=a*16+r][k] = rn(lora_A[a][e][k][r])

// ---------------- helpers ----------------
__device__ __forceinline__ uint32_t smem_u32(const void* p) {
    uint32_t a;
    asm("{ .reg .u64 t; cvta.to.shared.u64 t, %1; cvt.u32.u64 %0, t; }" : "=r"(a) : "l"(p));
    return a;
}
__device__ __forceinline__ void cp_async16(uint32_t dst, const void* src) {
    asm volatile("cp.async.cg.shared.global [%0], [%1], 16;"
                 :: "r"(dst), "l"(src) : "memory");
}
__device__ __forceinline__ void cp_async16p(uint32_t dst, const void* src, int srcsize) {
    asm volatile("cp.async.cg.shared.global [%0], [%1], 16, %2;"
                 :: "r"(dst), "l"(src), "r"(srcsize) : "memory");
}
__device__ __forceinline__ void ldsm_x4(uint32_t* r, uint32_t addr) {
    asm volatile("ldmatrix.sync.aligned.m8n8.x4.shared.b16 {%0,%1,%2,%3}, [%4];"
                 : "=r"(r[0]), "=r"(r[1]), "=r"(r[2]), "=r"(r[3]) : "r"(addr));
}

// Derive a row-tile from group_sizes. Returns false past the last tile.
__device__ __forceinline__ bool tile_lookup(const int* __restrict__ gs, int tile_id,
                                            int& row0, int& e, int& rows) {
    int cnt = 0, off = 0;
#pragma unroll
    for (int ee = 0; ee < NE; ee++) {
        int gsz = gs[ee];
        int nt  = (gsz + BM - 1) / BM;
        if (tile_id < cnt + nt) {
            int local = tile_id - cnt;
            row0 = off + local * BM;
            e    = ee;
            rows = min(BM, gsz - local * BM);
            return true;
        }
        cnt += nt;
        off += gsz;
    }
    return false;
}

// ---------------- kernel 1: uniform light prep ----------------
// [0, 1024)      : x -> fp16 into g_xe[:, 0:1024]
// [1024, 5120)   : W transpose + round into g_wt[:, :, 0:1024]
// [5120, 5376)   : lora_B extension into g_wt[:, :, 1024:1152]
// [5376, 5504)   : A_ext build into g_at
__global__ __launch_bounds__(256) void prep_kernel(
    const float* __restrict__ x,
    const float* __restrict__ wgt,
    const float* __restrict__ lA,
    const float* __restrict__ lB)
{
    __shared__ float tile[64][33];
    int b   = blockIdx.x;
    int tid = threadIdx.x;

    if (b < PB_XCONV) {
        // ---- x convert: 16 tokens, each thread one float4 column slot ----
        size_t t0 = (size_t)b * 16;
#pragma unroll
        for (int s = 0; s < 16; s++) {
            size_t t = t0 + s;
            float4 v = *(const float4*)&x[t * DIN + tid * 4];
            __half2* dst = (__half2*)&g_xe[t * KEXT + tid * 4];
            dst[0] = __floats2half2_rn(v.x, v.y);
            dst[1] = __floats2half2_rn(v.z, v.w);
        }
        return;
    }
    if (b < PB_XCONV + PB_WT) {
        // ---- W transpose: 64k x 32n tile ----
        int bid = b - PB_XCONV;
        int bx  = bid & 15;
        int by  = (bid >> 4) & 31;
        int e   = bid >> 9;
        int n0  = by * 32;
        int k0  = bx * 64;
        int tx  = tid & 31;
        int ty  = tid >> 5;
#pragma unroll
        for (int i = 0; i < 64; i += 8)
            tile[i + ty][tx] = wgt[((size_t)e * DIN + k0 + i + ty) * DOUT + n0 + tx];
        __syncthreads();
#pragma unroll
        for (int nn = 0; nn < 4; nn++) {
            int n = nn * 8 + ty;
            __half2 h = __floats2half2_rn(tile[tx * 2][n], tile[tx * 2 + 1][n]);
            *(__half2*)&g_wt[((size_t)e * DOUT + n0 + n) * KEXT + k0 + tx * 2] = h;
        }
        return;
    }
    if (b < PB_XCONV + PB_WT + PB_BEXT) {
        // ---- Bext: g_wt[e][n][1024 + a*16+r] = rn(lora_B[a][e][r][n]) ----
        int bid = b - PB_XCONV - PB_WT;
        int n0  = (bid & 31) * 32;
        int e   = bid >> 5;
        for (int f = tid; f < 32 * KLORA; f += 256) {
            int n = f >> 7;
            int j = f & 127;
            int a = j >> 4, r = j & 15;
            g_wt[((size_t)e * DOUT + n0 + n) * KEXT + DIN + j] =
                __float2half_rn(lB[(((size_t)a * NE + e) * RANK + r) * DOUT + n0 + n]);
        }
        return;
    }
    // ---- A_ext: one warp per (e, a, r): g_at[e][a*16+r][k] = rn(lora_A[a][e][k][r]) ----
    {
        int bid  = b - PB_XCONV - PB_WT - PB_BEXT;
        int w    = bid * 8 + (tid >> 5);     // 0..1023
        int lane = tid & 31;
        int e = w >> 7;
        int a = (w >> 4) & 7;
        int r = w & 15;
        const float* src = lA + ((size_t)(a * NE + e) * DIN) * RANK + r;
        __half* dst = g_at + ((size_t)e * KLORA + a * RANK + r) * DIN;
#pragma unroll
        for (int kb = 0; kb < DIN / 32; kb++) {
            int k = kb * 32 + lane;
            dst[k] = __float2half_rn(src[(size_t)k * RANK]);
        }
    }
}

// ---------------- kernel 2: inter-gemm  Y = x_tile @ A_ext^T, mask+scale -> g_xe[:,1024:] ----------------
__global__ __launch_bounds__(256, 2) void inter_gemm_kernel(
    const int* __restrict__ gs,
    const int* __restrict__ adap,
    const float* __restrict__ lscale)
{
    extern __shared__ char sm[];
    __shared__ int   adap_s[BM];
    __shared__ float scale_s[NA];

    int row0, e, rows;
    if (!tile_lookup(gs, blockIdx.x, row0, e, rows)) return;

    int tid  = threadIdx.x;
    int lane = tid & 31;
    int wid  = tid >> 5;
    int wm   = (wid & 3) * 32;
    int wn   = (wid >> 2) * 64;
    int gi   = lane >> 2;
    int ti   = lane & 3;

    if (tid < NA) scale_s[tid] = lscale[tid];
    if (tid < BM) adap_s[tid] = (tid < rows) ? adap[row0 + tid] : 0;
    __syncthreads();

    uint32_t sbase = smem_u32(sm);
    const __half* arow = g_xe + (size_t)row0 * KEXT;
    const __half* brow = g_at + (size_t)e * KLORA * DIN;

    uint32_t aoff[2];
#pragma unroll
    for (int i = 0; i < 2; i++)
        aoff[i] = (uint32_t)((wm + i * 16 + (lane & 15)) * RSTRIDE + (lane >> 4) * 8) * 2;
    uint32_t boff[4];
#pragma unroll
    for (int p = 0; p < 4; p++)
        boff[p] = (uint32_t)((wn + p * 16 + ((lane >> 4) << 3) + (lane & 7)) * RSTRIDE
                             + (((lane >> 3) & 1) << 3)) * 2;

    float acc[2][8][4];
#pragma unroll
    for (int i = 0; i < 2; i++)
#pragma unroll
        for (int j = 0; j < 8; j++)
#pragma unroll
            for (int q = 0; q < 4; q++) acc[i][j][q] = 0.f;

    bool full = (rows == BM);
    auto load_chunk = [&](int c) {
        uint32_t ab = sbase + (c & 1) * ABY;
        uint32_t bb = sbase + 2 * ABY + (c & 1) * ABY;
#pragma unroll
        for (int it = 0; it < 4; it++) {
            int f = tid + it * 256;
            int m = f >> 3, q = f & 7;
            if (full)
                cp_async16(ab + m * (RSTRIDE * 2) + q * 16,
                           arow + (size_t)m * KEXT + c * BK + q * 8);
            else
                cp_async16p(ab + m * (RSTRIDE * 2) + q * 16,
                            arow + (size_t)m * KEXT + c * BK + q * 8,
                            (m < rows) ? 16 : 0);
            cp_async16(bb + m * (RSTRIDE * 2) + q * 16,
                       brow + (size_t)m * DIN + c * BK + q * 8);
        }
    };

    load_chunk(0);
    asm volatile("cp.async.commit_group;" ::: "memory");

    for (int c = 0; c < NCHUNK_I; c++) {
        asm volatile("cp.async.wait_group 0;" ::: "memory");
        __syncthreads();
        if (c + 1 < NCHUNK_I) {
            load_chunk(c + 1);
            asm volatile("cp.async.commit_group;" ::: "memory");
        }
        uint32_t abase = sbase + (c & 1) * ABY;
        uint32_t bbase = sbase + 2 * ABY + (c & 1) * ABY;
#pragma unroll
        for (int t = 0; t < 4; t++) {
            uint32_t a[2][4], bmat[4][4];
#pragma unroll
            for (int i = 0; i < 2; i++) ldsm_x4(a[i], abase + aoff[i] + t * 32);
#pragma unroll
            for (int p = 0; p < 4; p++) ldsm_x4(bmat[p], bbase + boff[p] + t * 32);
#pragma unroll
            for (int i = 0; i < 2; i++)
#pragma unroll
                for (int j = 0; j < 8; j++) {
                    float* d = acc[i][j];
                    asm volatile(
                        "mma.sync.aligned.m16n8k16.row.col.f32.f16.f16.f32 "
                        "{%0,%1,%2,%3}, {%4,%5,%6,%7}, {%8,%9}, {%0,%1,%2,%3};"
                        : "+f"(d[0]), "+f"(d[1]), "+f"(d[2]), "+f"(d[3])
                        : "r"(a[i][0]), "r"(a[i][1]), "r"(a[i][2]), "r"(a[i][3]),
                          "r"(bmat[j >> 1][(j & 1) * 2]), "r"(bmat[j >> 1][(j & 1) * 2 + 1]));
                }
        }
    }

    // ---- epilogue: mask by adapter group, scale, write fp16 into g_xe[:, 1024:1152] ----
    __half2 hz = __floats2half2_rn(0.f, 0.f);
#pragma unroll
    for (int i = 0; i < 2; i++) {
        int r1 = wm + i * 16 + gi;
        int a0 = adap_s[r1];
        int a1 = adap_s[(r1 + 8) & 127];
        float s0 = scale_s[a0];
        float s1 = scale_s[a1];
#pragma unroll
        for (int j = 0; j < 8; j++) {
            int cn  = wn + j * 8 + ti * 2;
            int grp = cn >> 4;                // adapter owning these 2 cols (cn even, same group)
            if (r1 < rows) {
                __half2 h = (grp == a0)
                    ? __floats2half2_rn(s0 * acc[i][j][0], s0 * acc[i][j][1]) : hz;
                *(__half2*)&g_xe[(size_t)(row0 + r1) * KEXT + DIN + cn] = h;
            }
            if (r1 + 8 < rows) {
                __half2 h = (grp == a1)
                    ? __floats2half2_rn(s1 * acc[i][j][2], s1 * acc[i][j][3]) : hz;
                *(__half2*)&g_xe[(size_t)(row0 + r1 + 8) * KEXT + DIN + cn] = h;
            }
        }
    }
}

// ---------------- kernel 3: fp16 mma.sync GEMM, 128x128 tile, K = 1152 (unchanged) ----------------
__global__ __launch_bounds__(256, 2) void main_gemm_kernel(const int* __restrict__ gs,
                                                           float* __restrict__ out) {
    extern __shared__ char sm[];
    int row0, e, rows;
    if (!tile_lookup(gs, blockIdx.y, row0, e, rows)) return;

    int col0 = blockIdx.x * BN;
    int tid  = threadIdx.x;
    int lane = tid & 31;
    int wid  = tid >> 5;
    int wm   = (wid & 3) * 32;
    int wn   = (wid >> 2) * 64;
    int gi   = lane >> 2;
    int ti   = lane & 3;

    uint32_t sbase = smem_u32(sm);
    const __half* arow = g_xe + (size_t)row0 * KEXT;
    const __half* brow = g_wt + ((size_t)e * DOUT + col0) * KEXT;

    uint32_t aoff[2];
#pragma unroll
    for (int i = 0; i < 2; i++)
        aoff[i] = (uint32_t)((wm + i * 16 + (lane & 15)) * RSTRIDE + (lane >> 4) * 8) * 2;
    uint32_t boff[4];
#pragma unroll
    for (int p = 0; p < 4; p++)
        boff[p] = (uint32_t)((wn + p * 16 + ((lane >> 4) << 3) + (lane & 7)) * RSTRIDE
                             + (((lane >> 3) & 1) << 3)) * 2;

    float acc[2][8][4];
#pragma unroll
    for (int i = 0; i < 2; i++)
#pragma unroll
        for (int j = 0; j < 8; j++)
#pragma unroll
            for (int q = 0; q < 4; q++) acc[i][j][q] = 0.f;

    bool full = (rows == BM);
    auto load_chunk = [&](int c) {
        uint32_t ab = sbase + (c & 1) * ABY;
        uint32_t bb = sbase + 2 * ABY + (c & 1) * ABY;
        if (full) {
#pragma unroll
            for (int it = 0; it < 4; it++) {
                int f = tid + it * 256;
                int m = f >> 3, q = f & 7;
                cp_async16(ab + m * (RSTRIDE * 2) + q * 16,
                           arow + (size_t)m * KEXT + c * BK + q * 8);
                cp_async16(bb + m * (RSTRIDE * 2) + q * 16,
                           brow + (size_t)m * KEXT + c * BK + q * 8);
            }
        } else {
#pragma unroll
            for (int it = 0; it < 4; it++) {
                int f = tid + it * 256;
                int m = f >> 3, q = f & 7;
                cp_async16p(ab + m * (RSTRIDE * 2) + q * 16,
                            arow + (size_t)m * KEXT + c * BK + q * 8,
                            (m < rows) ? 16 : 0);
                cp_async16(bb + m * (RSTRIDE * 2) + q * 16,
                           brow + (size_t)m * KEXT + c * BK + q * 8);
            }
        }
    };

    load_chunk(0);
    asm volatile("cp.async.commit_group;" ::: "memory");

    for (int c = 0; c < NCHUNK; c++) {
        asm volatile("cp.async.wait_group 0;" ::: "memory");
        __syncthreads();
        if (c + 1 < NCHUNK) {
            load_chunk(c + 1);
            asm volatile("cp.async.commit_group;" ::: "memory");
        }
        uint32_t abase = sbase + (c & 1) * ABY;
        uint32_t bbase = sbase + 2 * ABY + (c & 1) * ABY;
#pragma unroll
        for (int t = 0; t < 4; t++) {
            uint32_t a[2][4], b[4][4];
#pragma unroll
            for (int i = 0; i < 2; i++) ldsm_x4(a[i], abase + aoff[i] + t * 32);
#pragma unroll
            for (int p = 0; p < 4; p++) ldsm_x4(b[p], bbase + boff[p] + t * 32);
#pragma unroll
            for (int i = 0; i < 2; i++)
#pragma unroll
                for (int j = 0; j < 8; j++) {
                    float* d = acc[i][j];
                    asm volatile(
                        "mma.sync.aligned.m16n8k16.row.col.f32.f16.f16.f32 "
                        "{%0,%1,%2,%3}, {%4,%5,%6,%7}, {%8,%9}, {%0,%1,%2,%3};"
                        : "+f"(d[0]), "+f"(d[1]), "+f"(d[2]), "+f"(d[3])
                        : "r"(a[i][0]), "r"(a[i][1]), "r"(a[i][2]), "r"(a[i][3]),
                          "r"(b[j >> 1][(j & 1) * 2]), "r"(b[j >> 1][(j & 1) * 2 + 1]));
                }
        }
    }

    float* obase = out + (size_t)row0 * DOUT + col0;
#pragma unroll
    for (int i = 0; i < 2; i++) {
        int r1 = wm + i * 16 + gi;
#pragma unroll
        for (int j = 0; j < 8; j++) {
            int cn = wn + j * 8 + ti * 2;
            if (r1 < rows)
                *(float2*)(obase + (size_t)r1 * DOUT + cn) =
                    make_float2(acc[i][j][0], acc[i][j][1]);
            if (r1 + 8 < rows)
                *(float2*)(obase + (size_t)(r1 + 8) * DOUT + cn) =
                    make_float2(acc[i][j][2], acc[i][j][3]);
        }
    }
}

// ---------------- launch ----------------
extern "C" void kernel_launch(void* const* d_in, const int* in_sizes, int n_in,
                              void* d_out, int out_size) {
    const float* x      = (const float*)d_in[0];
    const int*   gs     = (const int*)  d_in[1];
    const int*   adap   = (const int*)  d_in[2];
    const float* wgt    = (const float*)d_in[3];
    const float* lA     = (const float*)d_in[4];
    const float* lB     = (const float*)d_in[5];
    const float* lscale = (const float*)d_in[6];
    float*       out    = (float*)d_out;

    cudaFuncSetAttribute(main_gemm_kernel,
                         cudaFuncAttributeMaxDynamicSharedMemorySize, DSMEM_BYTES);
    cudaFuncSetAttribute(inter_gemm_kernel,
                         cudaFuncAttributeMaxDynamicSharedMemorySize, DSMEM_BYTES);

    prep_kernel<<<PB_TOTAL, 256>>>(x, wgt, lA, lB);
    inter_gemm_kernel<<<MAX_TILES, 256, DSMEM_BYTES>>>(gs, adap, lscale);
    main_gemm_kernel<<<dim3(DOUT / BN, MAX_TILES), 256, DSMEM_BYTES>>>(gs, out);
}

// round 15
// speedup vs baseline: 1.8811x; 1.2586x over previous
#include <cuda_runtime.h>
#include <cuda_fp16.h>
#include <cstdint>

#define T_TOK 16384
#define NE    8
#define DIN   1024
#define DOUT  1024
#define NA    8
#define RANK  16
#define BM    128
#define BK    64                    // halfs per K-chunk (128 bytes)
#define KLORA (NA * RANK)           // 128
#define KEXT  (DIN + KLORA)         // 1152
#define NCHUNK (KEXT / BK)          // 18
#define NCHUNK_I (DIN / BK)         // 16 (inter-gemm: K = 1024)
#define MAX_TILES 144
#define RSTRIDE 72                  // smem row stride in halfs (64 + 8 pad, 144B)

// inter-gemm smem: A(128) + B(128) double buffered
#define ABY_I   (BM * RSTRIDE * 2)          // 18432
#define DSMEM_I (4 * ABY_I)                 // 73728

// main gemm: 128x256 tile, A(128) + B(256) double buffered
#define BN_M    256
#define ABY_M   (BM * RSTRIDE * 2)          // 18432
#define BBY_M   (BN_M * RSTRIDE * 2)        // 36864
#define DSMEM_M (2 * ABY_M + 2 * BBY_M)     // 110592

// prep kernel block ranges
#define PB_WT    4096               // W transpose (16 x 32 x 8)
#define PB_BEXT  256                // lora_B extension (32 x 8)
#define PB_AEXT  128                // A_ext build (1024 warps)
#define PB_TOTAL (PB_WT + PB_BEXT + PB_AEXT)

// ---------------- device scratch (static, no allocations) ----------------
__device__ __align__(256) __half g_xe[(size_t)T_TOK * KEXT];     // 37.7 MB [rn(x) | masked scaled inter]
__device__ __align__(256) __half g_wt[(size_t)NE * DOUT * KEXT]; // 18.9 MB [e][n][k]: rn(W^T) | rn(lora_B)
__device__ __align__(256) __half g_at[(size_t)NE * KLORA * DIN]; // 2 MB [e][j=a*16+r][k] = rn(lora_A[a][e][k][r])

// ---------------- helpers ----------------
__device__ __forceinline__ uint32_t smem_u32(const void* p) {
    uint32_t a;
    asm("{ .reg .u64 t; cvta.to.shared.u64 t, %1; cvt.u32.u64 %0, t; }" : "=r"(a) : "l"(p));
    return a;
}
__device__ __forceinline__ void cp_async16(uint32_t dst, const void* src) {
    asm volatile("cp.async.cg.shared.global [%0], [%1], 16;"
                 :: "r"(dst), "l"(src) : "memory");
}
__device__ __forceinline__ void cp_async16p(uint32_t dst, const void* src, int srcsize) {
    asm volatile("cp.async.cg.shared.global [%0], [%1], 16, %2;"
                 :: "r"(dst), "l"(src), "r"(srcsize) : "memory");
}
__device__ __forceinline__ void ldsm_x4(uint32_t* r, uint32_t addr) {
    asm volatile("ldmatrix.sync.aligned.m8n8.x4.shared.b16 {%0,%1,%2,%3}, [%4];"
                 : "=r"(r[0]), "=r"(r[1]), "=r"(r[2]), "=r"(r[3]) : "r"(addr));
}
__device__ __forceinline__ bool tile_lookup(const int* __restrict__ gs, int tile_id,
                                            int& row0, int& e, int& rows) {
    int cnt = 0, off = 0;
#pragma unroll
    for (int ee = 0; ee < NE; ee++) {
        int gsz = gs[ee];
        int nt  = (gsz + BM - 1) / BM;
        if (tile_id < cnt + nt) {
            int local = tile_id - cnt;
            row0 = off + local * BM;
            e    = ee;
            rows = min(BM, gsz - local * BM);
            return true;
        }
        cnt += nt;
        off += gsz;
    }
    return false;
}

// ---------------- kernel 1: prep (W transpose + Bext + A_ext) ----------------
__global__ __launch_bounds__(256) void prep_kernel(
    const float* __restrict__ wgt,
    const float* __restrict__ lA,
    const float* __restrict__ lB)
{
    __shared__ float tile[64][33];
    int b   = blockIdx.x;
    int tid = threadIdx.x;

    if (b < PB_WT) {
        int bx  = b & 15;
        int by  = (b >> 4) & 31;
        int e   = b >> 9;
        int n0  = by * 32;
        int k0  = bx * 64;
        int tx  = tid & 31;
        int ty  = tid >> 5;
#pragma unroll
        for (int i = 0; i < 64; i += 8)
            tile[i + ty][tx] = wgt[((size_t)e * DIN + k0 + i + ty) * DOUT + n0 + tx];
        __syncthreads();
#pragma unroll
        for (int nn = 0; nn < 4; nn++) {
            int n = nn * 8 + ty;
            __half2 h = __floats2half2_rn(tile[tx * 2][n], tile[tx * 2 + 1][n]);
            *(__half2*)&g_wt[((size_t)e * DOUT + n0 + n) * KEXT + k0 + tx * 2] = h;
        }
        return;
    }
    if (b < PB_WT + PB_BEXT) {
        int bid = b - PB_WT;
        int n0  = (bid & 31) * 32;
        int e   = bid >> 5;
        for (int f = tid; f < 32 * KLORA; f += 256) {
            int n = f >> 7;
            int j = f & 127;
            int a = j >> 4, r = j & 15;
            g_wt[((size_t)e * DOUT + n0 + n) * KEXT + DIN + j] =
                __float2half_rn(lB[(((size_t)a * NE + e) * RANK + r) * DOUT + n0 + n]);
        }
        return;
    }
    {
        int bid  = b - PB_WT - PB_BEXT;
        int w    = bid * 8 + (tid >> 5);     // 0..1023
        int lane = tid & 31;
        int e = w >> 7;
        int a = (w >> 4) & 7;
        int r = w & 15;
        const float* src = lA + ((size_t)(a * NE + e) * DIN) * RANK + r;
        __half* dst = g_at + ((size_t)e * KLORA + a * RANK + r) * DIN;
#pragma unroll
        for (int kb = 0; kb < DIN / 32; kb++) {
            int k = kb * 32 + lane;
            dst[k] = __float2half_rn(src[(size_t)k * RANK]);
        }
    }
}

// ---------------- kernel 2: inter-gemm + fused x->fp16 ----------------
// Reads fp32 x, converts once (rn), uses for its own MMA AND writes g_xe[:, 0:1024].
// Then Y = x @ A_ext^T, masked+scaled -> g_xe[:, 1024:1152].
__global__ __launch_bounds__(256) void inter_gemm_kernel(
    const float* __restrict__ x,
    const int* __restrict__ gs,
    const int* __restrict__ adap,
    const float* __restrict__ lscale)
{
    extern __shared__ char sm[];
    __shared__ int   adap_s[BM];
    __shared__ float scale_s[NA];

    int row0, e, rows;
    if (!tile_lookup(gs, blockIdx.x, row0, e, rows)) return;

    int tid  = threadIdx.x;
    int lane = tid & 31;
    int wid  = tid >> 5;
    int wm   = (wid & 3) * 32;
    int wn   = (wid >> 2) * 64;
    int gi   = lane >> 2;
    int ti   = lane & 3;

    if (tid < NA) scale_s[tid] = lscale[tid];
    if (tid < BM) adap_s[tid] = (tid < rows) ? adap[row0 + tid] : 0;

    uint32_t sbase = smem_u32(sm);
    const float*  xrow = x + (size_t)row0 * DIN;
    const __half* brow = g_at + (size_t)e * KLORA * DIN;

    uint32_t aoff[2];
#pragma unroll
    for (int i = 0; i < 2; i++)
        aoff[i] = (uint32_t)((wm + i * 16 + (lane & 15)) * RSTRIDE + (lane >> 4) * 8) * 2;
    uint32_t boff[4];
#pragma unroll
    for (int p = 0; p < 4; p++)
        boff[p] = (uint32_t)((wn + p * 16 + ((lane >> 4) << 3) + (lane & 7)) * RSTRIDE
                             + (((lane >> 3) & 1) << 3)) * 2;

    float acc[2][8][4];
#pragma unroll
    for (int i = 0; i < 2; i++)
#pragma unroll
        for (int j = 0; j < 8; j++)
#pragma unroll
            for (int q = 0; q < 4; q++) acc[i][j][q] = 0.f;

    // per-thread A slots: f = tid + it*256, m = f>>4, q = f&15 (16 float4 per row)
    float4 av[8];
    auto ldg_a = [&](int c) {
#pragma unroll
        for (int it = 0; it < 8; it++) {
            int f = tid + it * 256;
            int m = f >> 4, q = f & 15;
            av[it] = (m < rows) ? *(const float4*)(xrow + (size_t)m * DIN + c * BK + q * 4)
                                : make_float4(0.f, 0.f, 0.f, 0.f);
        }
    };
    auto sts_stg_a = [&](int c) {
        uint32_t ab = sbase + (c & 1) * ABY_I;
#pragma unroll
        for (int it = 0; it < 8; it++) {
            int f = tid + it * 256;
            int m = f >> 4, q = f & 15;
            __half2 h0 = __floats2half2_rn(av[it].x, av[it].y);
            __half2 h1 = __floats2half2_rn(av[it].z, av[it].w);
            uint2 u = make_uint2(*(uint32_t*)&h0, *(uint32_t*)&h1);
            *(uint2*)(sm + ((ab - sbase) + m * (RSTRIDE * 2) + q * 8)) = u;
            if (m < rows)
                *(uint2*)&g_xe[(size_t)(row0 + m) * KEXT + c * BK + q * 4] = u;
        }
    };
    auto cp_b = [&](int c) {
        uint32_t bb = sbase + 2 * ABY_I + (c & 1) * ABY_I;
#pragma unroll
        for (int it = 0; it < 4; it++) {
            int f = tid + it * 256;
            int m = f >> 3, q = f & 7;
            cp_async16(bb + m * (RSTRIDE * 2) + q * 16,
                       brow + (size_t)m * DIN + c * BK + q * 8);
        }
    };

    // prologue: chunk 0
    ldg_a(0);
    cp_b(0);
    asm volatile("cp.async.commit_group;" ::: "memory");
    sts_stg_a(0);

    for (int c = 0; c < NCHUNK_I; c++) {
        asm volatile("cp.async.wait_group 0;" ::: "memory");
        __syncthreads();

        if (c + 1 < NCHUNK_I) {
            ldg_a(c + 1);                              // prefetch into regs
            cp_b(c + 1);
            asm volatile("cp.async.commit_group;" ::: "memory");
        }

        uint32_t abase = sbase + (c & 1) * ABY_I;
        uint32_t bbase = sbase + 2 * ABY_I + (c & 1) * ABY_I;
#pragma unroll
        for (int t = 0; t < 4; t++) {
            uint32_t a[2][4], bmat[4][4];
#pragma unroll
            for (int i = 0; i < 2; i++) ldsm_x4(a[i], abase + aoff[i] + t * 32);
#pragma unroll
            for (int p = 0; p < 4; p++) ldsm_x4(bmat[p], bbase + boff[p] + t * 32);
#pragma unroll
            for (int i = 0; i < 2; i++)
#pragma unroll
                for (int j = 0; j < 8; j++) {
                    float* d = acc[i][j];
                    asm volatile(
                        "mma.sync.aligned.m16n8k16.row.col.f32.f16.f16.f32 "
                        "{%0,%1,%2,%3}, {%4,%5,%6,%7}, {%8,%9}, {%0,%1,%2,%3};"
                        : "+f"(d[0]), "+f"(d[1]), "+f"(d[2]), "+f"(d[3])
                        : "r"(a[i][0]), "r"(a[i][1]), "r"(a[i][2]), "r"(a[i][3]),
                          "r"(bmat[j >> 1][(j & 1) * 2]), "r"(bmat[j >> 1][(j & 1) * 2 + 1]));
                }
        }

        if (c + 1 < NCHUNK_I)
            sts_stg_a(c + 1);   // other buffer; ordered by next iteration's sync
    }

    // ---- epilogue: mask by adapter, scale, write fp16 into g_xe[:, 1024:1152] ----
    __half2 hz = __floats2half2_rn(0.f, 0.f);
#pragma unroll
    for (int i = 0; i < 2; i++) {
        int r1 = wm + i * 16 + gi;
        int a0 = adap_s[r1];
        int a1 = adap_s[(r1 + 8) & 127];
        float s0 = scale_s[a0];
        float s1 = scale_s[a1];
#pragma unroll
        for (int j = 0; j < 8; j++) {
            int cn  = wn + j * 8 + ti * 2;
            int grp = cn >> 4;
            if (r1 < rows) {
                __half2 h = (grp == a0)
                    ? __floats2half2_rn(s0 * acc[i][j][0], s0 * acc[i][j][1]) : hz;
                *(__half2*)&g_xe[(size_t)(row0 + r1) * KEXT + DIN + cn] = h;
            }
            if (r1 + 8 < rows) {
                __half2 h = (grp == a1)
                    ? __floats2half2_rn(s1 * acc[i][j][2], s1 * acc[i][j][3]) : hz;
                *(__half2*)&g_xe[(size_t)(row0 + r1 + 8) * KEXT + DIN + cn] = h;
            }
        }
    }
}

// ---------------- kernel 3: fp16 mma.sync GEMM, 128x256 tile, 512 threads, K = 1152 ----------------
__global__ __launch_bounds__(512, 1) void main_gemm_kernel(const int* __restrict__ gs,
                                                           float* __restrict__ out) {
    extern __shared__ char sm[];
    int row0, e, rows;
    if (!tile_lookup(gs, blockIdx.y, row0, e, rows)) return;

    int col0 = blockIdx.x * BN_M;
    int tid  = threadIdx.x;
    int lane = tid & 31;
    int wid  = tid >> 5;           // 0..15
    int wm   = (wid & 3) * 32;     // 4 warps in M
    int wn   = (wid >> 2) * 64;    // 4 warps in N (256 cols)
    int gi   = lane >> 2;
    int ti   = lane & 3;

    uint32_t sbase = smem_u32(sm);
    const __half* arow = g_xe + (size_t)row0 * KEXT;
    const __half* brow = g_wt + ((size_t)e * DOUT + col0) * KEXT;

    uint32_t aoff[2];
#pragma unroll
    for (int i = 0; i < 2; i++)
        aoff[i] = (uint32_t)((wm + i * 16 + (lane & 15)) * RSTRIDE + (lane >> 4) * 8) * 2;
    uint32_t boff[4];
#pragma unroll
    for (int p = 0; p < 4; p++)
        boff[p] = (uint32_t)((wn + p * 16 + ((lane >> 4) << 3) + (lane & 7)) * RSTRIDE
                             + (((lane >> 3) & 1) << 3)) * 2;

    float acc[2][8][4];
#pragma unroll
    for (int i = 0; i < 2; i++)
#pragma unroll
        for (int j = 0; j < 8; j++)
#pragma unroll
            for (int q = 0; q < 4; q++) acc[i][j][q] = 0.f;

    bool full = (rows == BM);
    auto load_chunk = [&](int c) {
        uint32_t ab = sbase + (c & 1) * ABY_M;
        uint32_t bb = sbase + 2 * ABY_M + (c & 1) * BBY_M;
        // A: 128 rows x 8 slots = 1024 ops, 2 per thread
#pragma unroll
        for (int it = 0; it < 2; it++) {
            int f = tid + it * 512;
            int m = f >> 3, q = f & 7;
            if (full)
                cp_async16(ab + m * (RSTRIDE * 2) + q * 16,
                           arow + (size_t)m * KEXT + c * BK + q * 8);
            else
                cp_async16p(ab + m * (RSTRIDE * 2) + q * 16,
                            arow + (size_t)m * KEXT + c * BK + q * 8,
                            (m < rows) ? 16 : 0);
        }
        // B: 256 rows x 8 slots = 2048 ops, 4 per thread
#pragma unroll
        for (int it = 0; it < 4; it++) {
            int f = tid + it * 512;
            int m = f >> 3, q = f & 7;
            cp_async16(bb + m * (RSTRIDE * 2) + q * 16,
                       brow + (size_t)m * KEXT + c * BK + q * 8);
        }
    };

    load_chunk(0);
    asm volatile("cp.async.commit_group;" ::: "memory");

    for (int c = 0; c < NCHUNK; c++) {
        asm volatile("cp.async.wait_group 0;" ::: "memory");
        __syncthreads();
        if (c + 1 < NCHUNK) {
            load_chunk(c + 1);
            asm volatile("cp.async.commit_group;" ::: "memory");
        }
        uint32_t abase = sbase + (c & 1) * ABY_M;
        uint32_t bbase = sbase + 2 * ABY_M + (c & 1) * BBY_M;
#pragma unroll
        for (int t = 0; t < 4; t++) {
            uint32_t a[2][4], b[4][4];
#pragma unroll
            for (int i = 0; i < 2; i++) ldsm_x4(a[i], abase + aoff[i] + t * 32);
#pragma unroll
            for (int p = 0; p < 4; p++) ldsm_x4(b[p], bbase + boff[p] + t * 32);
#pragma unroll
            for (int i = 0; i < 2; i++)
#pragma unroll
                for (int j = 0; j < 8; j++) {
                    float* d = acc[i][j];
                    asm volatile(
                        "mma.sync.aligned.m16n8k16.row.col.f32.f16.f16.f32 "
                        "{%0,%1,%2,%3}, {%4,%5,%6,%7}, {%8,%9}, {%0,%1,%2,%3};"
                        : "+f"(d[0]), "+f"(d[1]), "+f"(d[2]), "+f"(d[3])
                        : "r"(a[i][0]), "r"(a[i][1]), "r"(a[i][2]), "r"(a[i][3]),
                          "r"(b[j >> 1][(j & 1) * 2]), "r"(b[j >> 1][(j & 1) * 2 + 1]));
                }
        }
    }

    float* obase = out + (size_t)row0 * DOUT + col0;
#pragma unroll
    for (int i = 0; i < 2; i++) {
        int r1 = wm + i * 16 + gi;
#pragma unroll
        for (int j = 0; j < 8; j++) {
            int cn = wn + j * 8 + ti * 2;
            if (r1 < rows)
                *(float2*)(obase + (size_t)r1 * DOUT + cn) =
                    make_float2(acc[i][j][0], acc[i][j][1]);
            if (r1 + 8 < rows)
                *(float2*)(obase + (size_t)(r1 + 8) * DOUT + cn) =
                    make_float2(acc[i][j][2], acc[i][j][3]);
        }
    }
}

// ---------------- launch ----------------
extern "C" void kernel_launch(void* const* d_in, const int* in_sizes, int n_in,
                              void* d_out, int out_size) {
    const float* x      = (const float*)d_in[0];
    const int*   gs     = (const int*)  d_in[1];
    const int*   adap   = (const int*)  d_in[2];
    const float* wgt    = (const float*)d_in[3];
    const float* lA     = (const float*)d_in[4];
    const float* lB     = (const float*)d_in[5];
    const float* lscale = (const float*)d_in[6];
    float*       out    = (float*)d_out;

    cudaFuncSetAttribute(main_gemm_kernel,
                         cudaFuncAttributeMaxDynamicSharedMemorySize, DSMEM_M);
    cudaFuncSetAttribute(inter_gemm_kernel,
                         cudaFuncAttributeMaxDynamicSharedMemorySize, DSMEM_I);

    prep_kernel<<<PB_TOTAL, 256>>>(wgt, lA, lB);
    inter_gemm_kernel<<<MAX_TILES, 256, DSMEM_I>>>(x, gs, adap, lscale);
    main_gemm_kernel<<<dim3(DOUT / BN_M, MAX_TILES), 512, DSMEM_M>>>(gs, out);
}